// round 8
// baseline (speedup 1.0000x reference)
#include <cuda_runtime.h>
#include <cuda_bf16.h>
#include <cuda_fp16.h>
#include <cstdint>

#define SCALE_ 0.125f   // 1/sqrt(64)

// GEMM operands: fp16 pairs (u32 = 2 fp16 along k) + e4m3 quads (u32 = 4 e4m3 along k)
__device__ uint32_t g_xhp [4096*512], g_xe4h[4096*256], g_xe4l[4096*256];
__device__ uint32_t g_wqhp[512*3072], g_wqe4h[256*3072], g_wqe4l[256*3072];
__device__ float    g_of32[4096*1024];
__device__ uint32_t g_ohp [4096*512], g_oe4h[4096*256], g_oe4l[4096*256];
__device__ uint32_t g_wohp[512*1024], g_woe4h[256*1024], g_woe4l[256*1024];

// attention operands, packed bf16x2 hi/lo (unchanged, validated)
__device__ uint32_t g_qh [32*2048*32], g_ql [32*2048*32]; // Q  [bh][l][dk2]
__device__ uint32_t g_kh [32*32*2048], g_kl [32*32*2048]; // K  [bh][dk2][l]
__device__ uint32_t g_vth[32*2048*32], g_vtl[32*2048*32]; // Vt [bh][l][dk2]
__device__ uint32_t g_vh [32*1024*64], g_vl [32*1024*64]; // V  [bh][l2][dk]
__device__ uint32_t g_mb [2*2048*64];                     // mask bits

// ---------------------------------------------------------------------------
// Helpers
// ---------------------------------------------------------------------------
__device__ __forceinline__ uint32_t pack_hl(float a, float b, uint32_t& lo) {
    __nv_bfloat162 t, u;
    t.x = __float2bfloat16_rn(a);
    t.y = __float2bfloat16_rn(b);
    u.x = __float2bfloat16_rn(a - __bfloat162float(t.x));
    u.y = __float2bfloat16_rn(b - __bfloat162float(t.y));
    lo = *reinterpret_cast<uint32_t*>(&u);
    return *reinterpret_cast<uint32_t*>(&t);
}
__device__ __forceinline__ uint32_t pack_h2(float a, float b) {
    __half2 h = __floats2half2_rn(a, b);    // x=a (low), y=b (high)
    return *reinterpret_cast<uint32_t*>(&h);
}
__device__ __forceinline__ uint32_t pack_e4(float v0, float v1, float v2, float v3) {
    uint16_t w01, w23;
    asm("cvt.rn.satfinite.e4m3x2.f32 %0, %1, %2;" : "=h"(w01) : "f"(v1), "f"(v0));
    asm("cvt.rn.satfinite.e4m3x2.f32 %0, %1, %2;" : "=h"(w23) : "f"(v3), "f"(v2));
    return (uint32_t)w01 | ((uint32_t)w23 << 16);
}
__device__ __forceinline__ void cp16(uint32_t saddr, const void* gptr) {
    asm volatile("cp.async.cg.shared.global [%0], [%1], 16;\n" :: "r"(saddr), "l"(gptr));
}
__device__ __forceinline__ void cp_commit() {
    asm volatile("cp.async.commit_group;\n" ::: "memory");
}
__device__ __forceinline__ void mma16816(float* c, const uint32_t* a, const uint32_t* b) {
    asm volatile(
        "mma.sync.aligned.m16n8k16.row.col.f32.bf16.bf16.f32 "
        "{%0,%1,%2,%3}, {%4,%5,%6,%7}, {%8,%9}, {%0,%1,%2,%3};\n"
        : "+f"(c[0]), "+f"(c[1]), "+f"(c[2]), "+f"(c[3])
        : "r"(a[0]), "r"(a[1]), "r"(a[2]), "r"(a[3]), "r"(b[0]), "r"(b[1]));
}
__device__ __forceinline__ void mma_f16(float* c, const uint32_t* a, const uint32_t* b) {
    asm volatile(
        "mma.sync.aligned.m16n8k16.row.col.f32.f16.f16.f32 "
        "{%0,%1,%2,%3}, {%4,%5,%6,%7}, {%8,%9}, {%0,%1,%2,%3};\n"
        : "+f"(c[0]), "+f"(c[1]), "+f"(c[2]), "+f"(c[3])
        : "r"(a[0]), "r"(a[1]), "r"(a[2]), "r"(a[3]), "r"(b[0]), "r"(b[1]));
}
__device__ __forceinline__ void mma_e4(float* c, const uint32_t* a, const uint32_t* b) {
    asm volatile(
        "mma.sync.aligned.m16n8k32.row.col.f32.e4m3.e4m3.f32 "
        "{%0,%1,%2,%3}, {%4,%5,%6,%7}, {%8,%9}, {%0,%1,%2,%3};\n"
        : "+f"(c[0]), "+f"(c[1]), "+f"(c[2]), "+f"(c[3])
        : "r"(a[0]), "r"(a[1]), "r"(a[2]), "r"(a[3]), "r"(b[0]), "r"(b[1]));
}

// ---------------------------------------------------------------------------
// Operand prep kernels
// ---------------------------------------------------------------------------
// A [M][1024] f32 -> fp16 pairs + e4m3 quads (hi, lo*2048)
__global__ void split_ax(const float* __restrict__ in, uint32_t* __restrict__ hp,
                         uint32_t* __restrict__ e4h, uint32_t* __restrict__ e4l, int n4)
{
    int i = blockIdx.x * 256 + threadIdx.x;
    if (i >= n4) return;
    float4 v = ((const float4*)in)[i];
    uint32_t h0 = pack_h2(v.x, v.y), h1 = pack_h2(v.z, v.w);
    hp[2*i] = h0; hp[2*i+1] = h1;
    __half2 H0 = *reinterpret_cast<__half2*>(&h0);
    __half2 H1 = *reinterpret_cast<__half2*>(&h1);
    float r0 = (v.x - __half2float(H0.x)) * 2048.f;
    float r1 = (v.y - __half2float(H0.y)) * 2048.f;
    float r2 = (v.z - __half2float(H1.x)) * 2048.f;
    float r3 = (v.w - __half2float(H1.y)) * 2048.f;
    e4h[i] = pack_e4(v.x, v.y, v.z, v.w);
    e4l[i] = pack_e4(r0, r1, r2, r3);
}

// W [1024][N] f32 -> fp16 pairs [512][N] + e4m3 quads [256][N]
__global__ void split_w(const float* __restrict__ in, uint32_t* __restrict__ hp,
                        uint32_t* __restrict__ e4h, uint32_t* __restrict__ e4l, int N)
{
    int n  = blockIdx.x * blockDim.x + threadIdx.x;
    int k4 = blockIdx.y;
    float v0 = in[(size_t)(4*k4+0)*N + n];
    float v1 = in[(size_t)(4*k4+1)*N + n];
    float v2 = in[(size_t)(4*k4+2)*N + n];
    float v3 = in[(size_t)(4*k4+3)*N + n];
    uint32_t h0 = pack_h2(v0, v1), h1 = pack_h2(v2, v3);
    hp[(size_t)(2*k4)*N + n]   = h0;
    hp[(size_t)(2*k4+1)*N + n] = h1;
    __half2 H0 = *reinterpret_cast<__half2*>(&h0);
    __half2 H1 = *reinterpret_cast<__half2*>(&h1);
    float r0 = (v0 - __half2float(H0.x)) * 2048.f;
    float r1 = (v1 - __half2float(H0.y)) * 2048.f;
    float r2 = (v2 - __half2float(H1.x)) * 2048.f;
    float r3 = (v3 - __half2float(H1.y)) * 2048.f;
    e4h[(size_t)k4*N + n] = pack_e4(v0, v1, v2, v3);
    e4l[(size_t)k4*N + n] = pack_e4(r0, r1, r2, r3);
}

__global__ void maskpack(const int* __restrict__ mask)
{
    int idx = blockIdx.x * 256 + threadIdx.x;
    int w   = idx & 63;
    int row = idx >> 6;
    const int4* p = (const int4*)(mask + (size_t)row * 2048 + w * 32);
    uint32_t bits = 0;
#pragma unroll
    for (int i = 0; i < 8; i++) {
        int4 v = p[i];
        bits |= (uint32_t)(v.x != 0) << (4*i)
             |  (uint32_t)(v.y != 0) << (4*i+1)
             |  (uint32_t)(v.z != 0) << (4*i+2)
             |  (uint32_t)(v.w != 0) << (4*i+3);
    }
    g_mb[idx] = bits;
}

__global__ void vrepack()
{
    int idx = blockIdx.x * 256 + threadIdx.x;
    int d  = idx & 63;
    int l2 = (idx >> 6) & 1023;
    int bh = idx >> 16;
    const uint16_t* th = (const uint16_t*)g_vth;
    const uint16_t* tl = (const uint16_t*)g_vtl;
    size_t i0 = ((size_t)bh*2048 + 2*l2    ) * 64 + d;
    size_t i1 = ((size_t)bh*2048 + 2*l2 + 1) * 64 + d;
    g_vh[idx] = (uint32_t)th[i0] | ((uint32_t)th[i1] << 16);
    g_vl[idx] = (uint32_t)tl[i0] | ((uint32_t)tl[i1] << 16);
}

// ---------------------------------------------------------------------------
// fp16+fp8 GEMM: C = A*B, block 128x128, K-tile 32, 256 threads (8 warps 64x32).
// Per k16: one f16 MMA (hi*hi) + one e4m3 k32 MMA (both cross terms, scaled 2^11).
// EPI=0: QKV epilogue -> packed bf16 Q/K/Vt.  EPI=1: f32 write + bias.
// ---------------------------------------------------------------------------
#define OA    0
#define OAH4  2560
#define OAL4  4096
#define OB    5632
#define OBH4  7808
#define OBL4  8896
#define STG   9984
#define GEMM_SMEM (2*STG*4)   // 79872 B

template<int EPI>
__global__ void __launch_bounds__(256, 1)
gemm_f16fp8(const uint32_t* __restrict__ Ahp, const uint32_t* __restrict__ Ae4h,
            const uint32_t* __restrict__ Ae4l,
            const uint32_t* __restrict__ Bhp, const uint32_t* __restrict__ Be4h,
            const uint32_t* __restrict__ Be4l,
            const float* __restrict__ bias, float* __restrict__ outp, int N)
{
    extern __shared__ uint32_t sm[];
    const int tid  = threadIdx.x;
    const int lane = tid & 31;
    const int wid  = tid >> 5;
    const int wm   = wid >> 2;      // 0..1 -> 64-row band
    const int wn   = wid & 3;       // 0..3 -> 32-col band
    const int c    = lane & 3;
    const int rq   = lane >> 2;
    const int m0   = blockIdx.y * 128;
    const int n0   = blockIdx.x * 128;

    const uint32_t sbase = (uint32_t)__cvta_generic_to_shared(sm);

    float C[4][4][4], Cx[4][4][4];
#pragma unroll
    for (int mt = 0; mt < 4; mt++)
#pragma unroll
        for (int nt = 0; nt < 4; nt++)
#pragma unroll
            for (int e = 0; e < 4; e++) { C[mt][nt][e] = 0.f; Cx[mt][nt][e] = 0.f; }

    auto load_stage = [&](int s, int t) {
        const uint32_t sa = sbase + (uint32_t)(s * STG) * 4;
        const int kp0 = t * 16, k40 = t * 8;
#pragma unroll
        for (int j = tid; j < 512; j += 256) {      // A fp16
            const int row = j >> 2, c4 = (j & 3) << 2;
            cp16(sa + (OA + row*20 + c4)*4, Ahp + (size_t)(m0+row)*512 + kp0 + c4);
        }
#pragma unroll
        for (int j = tid; j < 512; j += 256) {      // A e4m3 (hi, lo)
            const int row = j >> 2, sel = j & 3;
            const uint32_t* src = (sel < 2) ? Ae4h : Ae4l;
            const int off = (sel & 1) * 4;
            cp16(sa + (((sel < 2) ? OAH4 : OAL4) + row*12 + off)*4,
                 src + (size_t)(m0+row)*256 + k40 + off);
        }
#pragma unroll
        for (int j = tid; j < 512; j += 256) {      // B fp16
            const int row = j >> 5, c4 = (j & 31) << 2;
            cp16(sa + (OB + row*136 + c4)*4, Bhp + (size_t)(kp0+row)*N + n0 + c4);
        }
#pragma unroll
        for (int j = tid; j < 512; j += 256) {      // B e4m3 (hi, lo)
            const int sel = j >> 8, row = (j >> 5) & 7, c4 = (j & 31) << 2;
            const uint32_t* src = sel ? Be4l : Be4h;
            cp16(sa + ((sel ? OBL4 : OBH4) + row*136 + c4)*4,
                 src + (size_t)(k40+row)*N + n0 + c4);
        }
        cp_commit();
    };

    load_stage(0, 0);
    cp_commit();

    const int T = 32;
    for (int t = 0; t < T; t++) {
        if (t + 1 < T) { load_stage((t+1)&1, t+1); }
        if (t + 1 < T) asm volatile("cp.async.wait_group 1;\n" ::: "memory");
        else           asm volatile("cp.async.wait_group 0;\n" ::: "memory");
        __syncthreads();

        const uint32_t* S = sm + (t & 1) * STG;
#pragma unroll
        for (int ss = 0; ss < 2; ss++) {
            uint32_t ah[4][4], a8[4][4];
#pragma unroll
            for (int mt = 0; mt < 4; mt++) {
                const int r0 = wm*64 + mt*16 + rq;
                ah[mt][0] = S[OA + r0*20     + ss*8 + c];
                ah[mt][1] = S[OA + (r0+8)*20 + ss*8 + c];
                ah[mt][2] = S[OA + r0*20     + ss*8 + c + 4];
                ah[mt][3] = S[OA + (r0+8)*20 + ss*8 + c + 4];
                a8[mt][0] = S[OAH4 + r0*12     + ss*4 + c];
                a8[mt][1] = S[OAH4 + (r0+8)*12 + ss*4 + c];
                a8[mt][2] = S[OAL4 + r0*12     + ss*4 + c];
                a8[mt][3] = S[OAL4 + (r0+8)*12 + ss*4 + c];
            }
            uint32_t bh[4][2], b8[4][2];
            const int k2  = ss*8 + c;
            const int k4r = ss*4 + c;
#pragma unroll
            for (int nt = 0; nt < 4; nt++) {
                const int col = wn*32 + nt*8 + rq;
                bh[nt][0] = S[OB + k2*136     + col];
                bh[nt][1] = S[OB + (k2+4)*136 + col];
                b8[nt][0] = S[OBL4 + k4r*136 + col];   // slots 0-15 : wl*2^11
                b8[nt][1] = S[OBH4 + k4r*136 + col];   // slots 16-31: wh
            }
#pragma unroll
            for (int mt = 0; mt < 4; mt++)
#pragma unroll
                for (int nt = 0; nt < 4; nt++)
                    mma_f16(C[mt][nt], ah[mt], bh[nt]);
#pragma unroll
            for (int mt = 0; mt < 4; mt++)
#pragma unroll
                for (int nt = 0; nt < 4; nt++)
                    mma_e4(Cx[mt][nt], a8[mt], b8[nt]);
        }
        __syncthreads();
    }

    const float INV = 1.f / 2048.f;
    // Epilogue
#pragma unroll
    for (int mt = 0; mt < 4; mt++) {
#pragma unroll
        for (int nt = 0; nt < 4; nt++) {
            const int r  = m0 + wm*64 + mt*16 + rq;
            const int cc = n0 + wn*32 + nt*8 + c*2;
            const float b0 = bias[cc], b1 = bias[cc+1];
            const float v00 = C[mt][nt][0] + Cx[mt][nt][0]*INV + b0;
            const float v01 = C[mt][nt][1] + Cx[mt][nt][1]*INV + b1;
            const float v10 = C[mt][nt][2] + Cx[mt][nt][2]*INV + b0;
            const float v11 = C[mt][nt][3] + Cx[mt][nt][3]*INV + b1;
            if (EPI == 0) {
                const int part = cc >> 10;
                const int d    = cc & 1023;
                const int h    = d >> 6;
                const int dk2  = (d & 63) >> 1;
                const int bI   = r >> 11;
                const int l    = r & 2047;
                const int bhI  = bI*16 + h;
                uint32_t lo0, lo1;
                uint32_t hi0 = pack_hl(v00, v01, lo0);
                uint32_t hi1 = pack_hl(v10, v11, lo1);
                if (part == 0) {
                    size_t i0 = ((size_t)bhI*2048 + l)*32 + dk2;
                    g_qh[i0] = hi0;        g_ql[i0] = lo0;
                    g_qh[i0 + 8*32] = hi1; g_ql[i0 + 8*32] = lo1;
                } else if (part == 1) {
                    size_t i0 = ((size_t)bhI*32 + dk2)*2048 + l;
                    g_kh[i0]     = hi0;  g_kl[i0]     = lo0;
                    g_kh[i0 + 8] = hi1;  g_kl[i0 + 8] = lo1;
                } else {
                    size_t i0 = ((size_t)bhI*2048 + l)*32 + dk2;
                    g_vth[i0] = hi0;        g_vtl[i0] = lo0;
                    g_vth[i0 + 8*32] = hi1; g_vtl[i0 + 8*32] = lo1;
                }
            } else {
                *(float2*)&outp[(size_t)r*N + cc]     = make_float2(v00, v01);
                *(float2*)&outp[(size_t)(r+8)*N + cc] = make_float2(v10, v11);
            }
        }
    }
}

// ---------------------------------------------------------------------------
// Tensor-core flash attention (bf16x3 mma.sync, validated). 128 queries/CTA.
// Epilogue now writes f32 O (split kernel regenerates out-proj operands).
// ---------------------------------------------------------------------------
#define AKH 0
#define AKL 2304
#define AVH 4608
#define AVL 6912
#define ASTG 9216
#define ATTN_SMEM (2*ASTG*4)   // 73728 bytes

__device__ __forceinline__ void softmax_row(float (&sC)[8][4], float (&oC)[8][4],
                                            int e0, uint32_t w0, uint32_t w1,
                                            int c, float& mi, float& li)
{
    float rm = -1e30f;
    uint32_t rbits = 0;
#pragma unroll
    for (int j = 0; j < 8; j++) {
        const uint32_t w = (j < 4) ? w0 : w1;
#pragma unroll
        for (int e = 0; e < 2; e++) {
            const int col = 8*j + 2*c + e;
            const uint32_t bit = (w >> (col & 31)) & 1u;
            const float sv = bit ? sC[j][e0+e]*SCALE_ : 0.f;
            sC[j][e0+e] = sv;
            rbits |= bit << (2*j + e);
            rm = fmaxf(rm, sv);
        }
    }
    rm = fmaxf(rm, __shfl_xor_sync(0xffffffffu, rm, 1));
    rm = fmaxf(rm, __shfl_xor_sync(0xffffffffu, rm, 2));
    const float mn  = fmaxf(mi, rm);
    const float fac = __expf(mi - mn);
    float rs = 0.f;
#pragma unroll
    for (int j = 0; j < 8; j++)
#pragma unroll
        for (int e = 0; e < 2; e++) {
            const float pd = __expf(sC[j][e0+e] - mn);
            rs += pd;
            sC[j][e0+e] = ((rbits >> (2*j + e)) & 1u) ? pd : 0.f;
        }
    rs += __shfl_xor_sync(0xffffffffu, rs, 1);
    rs += __shfl_xor_sync(0xffffffffu, rs, 2);
    li = li*fac + rs;
    mi = mn;
#pragma unroll
    for (int j = 0; j < 8; j++) { oC[j][e0] *= fac; oC[j][e0+1] *= fac; }
}

__global__ void __launch_bounds__(256, 1)
attn_mma_kernel()
{
    extern __shared__ uint32_t sm[];
    const int tid  = threadIdx.x;
    const int lane = tid & 31;
    const int wid  = tid >> 5;
    const int c    = lane & 3;
    const int rq   = lane >> 2;
    const int bh   = blockIdx.y;
    const int b    = bh >> 4;
    const int h    = bh & 15;
    const int q0   = blockIdx.x * 128;
    const int r0   = q0 + wid*16 + rq;

    const uint32_t sbase = (uint32_t)__cvta_generic_to_shared(sm);

    uint32_t qh[4][4], ql[4][4];
    {
        const uint32_t* Qh = g_qh + (size_t)bh*2048*32;
        const uint32_t* Ql = g_ql + (size_t)bh*2048*32;
#pragma unroll
        for (int t = 0; t < 4; t++) {
            qh[t][0] = Qh[(size_t)r0*32     + 8*t + c];
            qh[t][1] = Qh[(size_t)(r0+8)*32 + 8*t + c];
            qh[t][2] = Qh[(size_t)r0*32     + 8*t + c + 4];
            qh[t][3] = Qh[(size_t)(r0+8)*32 + 8*t + c + 4];
            ql[t][0] = Ql[(size_t)r0*32     + 8*t + c];
            ql[t][1] = Ql[(size_t)(r0+8)*32 + 8*t + c];
            ql[t][2] = Ql[(size_t)r0*32     + 8*t + c + 4];
            ql[t][3] = Ql[(size_t)(r0+8)*32 + 8*t + c + 4];
        }
    }

    float oC[8][4];
#pragma unroll
    for (int j = 0; j < 8; j++)
#pragma unroll
        for (int e = 0; e < 4; e++) oC[j][e] = 0.f;
    float mi[2] = {-1e30f, -1e30f};
    float li[2] = {0.f, 0.f};

    auto load_stage = [&](int s, int k0) {
        const uint32_t sa = sbase + (uint32_t)(s * ASTG) * 4;
#pragma unroll
        for (int it = 0; it < 2; it++) {
            const int idx = it*256 + tid;
            const int row = idx >> 4;
            const int c4  = (idx & 15) * 4;
            cp16(sa + (AKH + row*72 + c4)*4, g_kh + ((size_t)bh*32 + row)*2048 + k0 + c4);
            cp16(sa + (AKL + row*72 + c4)*4, g_kl + ((size_t)bh*32 + row)*2048 + k0 + c4);
            cp16(sa + (AVH + row*72 + c4)*4, g_vh + ((size_t)bh*1024 + (k0>>1) + row)*64 + c4);
            cp16(sa + (AVL + row*72 + c4)*4, g_vl + ((size_t)bh*1024 + (k0>>1) + row)*64 + c4);
        }
    };

    load_stage(0, 0);
    cp_commit();

    const uint32_t* MB = g_mb + (size_t)b*2048*64;

    for (int t32 = 0; t32 < 32; t32++) {
        const int k0 = t32 * 64;
        if (t32 + 1 < 32) { load_stage((t32+1)&1, k0 + 64); cp_commit(); }
        if (t32 + 1 < 32) asm volatile("cp.async.wait_group 1;\n" ::: "memory");
        else              asm volatile("cp.async.wait_group 0;\n" ::: "memory");
        __syncthreads();

        const uint32_t* S = sm + (t32 & 1) * ASTG;

        float sC[8][4];
#pragma unroll
        for (int j = 0; j < 8; j++)
#pragma unroll
            for (int e = 0; e < 4; e++) sC[j][e] = 0.f;

#pragma unroll
        for (int t = 0; t < 4; t++) {
#pragma unroll
            for (int jj = 0; jj < 4; jj++) {
                const int j0 = 2*jj, j1 = 2*jj + 1;
                uint32_t b0h[2], b0l[2], b1h[2], b1l[2];
                b0h[0] = S[AKH + (8*t + c)*72     + 8*j0 + rq];
                b0h[1] = S[AKH + (8*t + c + 4)*72 + 8*j0 + rq];
                b0l[0] = S[AKL + (8*t + c)*72     + 8*j0 + rq];
                b0l[1] = S[AKL + (8*t + c + 4)*72 + 8*j0 + rq];
                b1h[0] = S[AKH + (8*t + c)*72     + 8*j1 + rq];
                b1h[1] = S[AKH + (8*t + c + 4)*72 + 8*j1 + rq];
                b1l[0] = S[AKL + (8*t + c)*72     + 8*j1 + rq];
                b1l[1] = S[AKL + (8*t + c + 4)*72 + 8*j1 + rq];
                mma16816(sC[j0], qh[t], b0h);
                mma16816(sC[j1], qh[t], b1h);
                mma16816(sC[j0], qh[t], b0l);
                mma16816(sC[j1], qh[t], b1l);
                mma16816(sC[j0], ql[t], b0h);
                mma16816(sC[j1], ql[t], b1h);
            }
        }

        const int wbase = k0 >> 5;
        const uint32_t w00 = MB[(size_t)r0*64 + wbase],     w01 = MB[(size_t)r0*64 + wbase + 1];
        const uint32_t w10 = MB[(size_t)(r0+8)*64 + wbase], w11 = MB[(size_t)(r0+8)*64 + wbase + 1];
        softmax_row(sC, oC, 0, w00, w01, c, mi[0], li[0]);
        softmax_row(sC, oC, 2, w10, w11, c, mi[1], li[1]);

#pragma unroll
        for (int tp = 0; tp < 4; tp++) {
            uint32_t pah[4], pal[4];
            pah[0] = pack_hl(sC[2*tp][0],   sC[2*tp][1],   pal[0]);
            pah[1] = pack_hl(sC[2*tp][2],   sC[2*tp][3],   pal[1]);
            pah[2] = pack_hl(sC[2*tp+1][0], sC[2*tp+1][1], pal[2]);
            pah[3] = pack_hl(sC[2*tp+1][2], sC[2*tp+1][3], pal[3]);
#pragma unroll
            for (int jj = 0; jj < 4; jj++) {
                const int j0 = 2*jj, j1 = 2*jj + 1;
                uint32_t b0h[2], b0l[2], b1h[2], b1l[2];
                b0h[0] = S[AVH + (8*tp + c)*72     + 8*j0 + rq];
                b0h[1] = S[AVH + (8*tp + c + 4)*72 + 8*j0 + rq];
                b0l[0] = S[AVL + (8*tp + c)*72     + 8*j0 + rq];
                b0l[1] = S[AVL + (8*tp + c + 4)*72 + 8*j0 + rq];
                b1h[0] = S[AVH + (8*tp + c)*72     + 8*j1 + rq];
                b1h[1] = S[AVH + (8*tp + c + 4)*72 + 8*j1 + rq];
                b1l[0] = S[AVL + (8*tp + c)*72     + 8*j1 + rq];
                b1l[1] = S[AVL + (8*tp + c + 4)*72 + 8*j1 + rq];
                mma16816(oC[j0], pah, b0h);
                mma16816(oC[j1], pah, b1h);
                mma16816(oC[j0], pah, b0l);
                mma16816(oC[j1], pah, b1l);
                mma16816(oC[j0], pal, b0h);
                mma16816(oC[j1], pal, b1h);
            }
        }
        __syncthreads();
    }

    // Normalize + f32 store
    const float inv0 = 1.0f / li[0];
    const float inv1 = 1.0f / li[1];
    const size_t row0 = (size_t)b*2048 + r0;
#pragma unroll
    for (int j = 0; j < 8; j++) {
        const int cc = h*64 + 8*j + 2*c;
        *(float2*)&g_of32[row0*1024 + cc]     = make_float2(oC[j][0]*inv0, oC[j][1]*inv0);
        *(float2*)&g_of32[(row0+8)*1024 + cc] = make_float2(oC[j][2]*inv1, oC[j][3]*inv1);
    }
}

// ---------------------------------------------------------------------------

extern "C" void kernel_launch(void* const* d_in, const int* in_sizes, int n_in,
                              void* d_out, int out_size)
{
    const float* x     = (const float*)d_in[0];
    const int*   mask  = (const int*)  d_in[1];
    const float* W_qkv = (const float*)d_in[2];
    const float* b_qkv = (const float*)d_in[3];
    const float* W_out = (const float*)d_in[4];
    const float* b_out = (const float*)d_in[5];
    float* out = (float*)d_out;

    cudaFuncSetAttribute(gemm_f16fp8<0>, cudaFuncAttributeMaxDynamicSharedMemorySize, GEMM_SMEM);
    cudaFuncSetAttribute(gemm_f16fp8<1>, cudaFuncAttributeMaxDynamicSharedMemorySize, GEMM_SMEM);
    cudaFuncSetAttribute(attn_mma_kernel, cudaFuncAttributeMaxDynamicSharedMemorySize, ATTN_SMEM);

    uint32_t *xhp, *xe4h, *xe4l, *wqhp, *wqe4h, *wqe4l;
    uint32_t *ohp, *oe4h, *oe4l, *wohp, *woe4h, *woe4l;
    float* of32;
    cudaGetSymbolAddress((void**)&xhp,   g_xhp);
    cudaGetSymbolAddress((void**)&xe4h,  g_xe4h);
    cudaGetSymbolAddress((void**)&xe4l,  g_xe4l);
    cudaGetSymbolAddress((void**)&wqhp,  g_wqhp);
    cudaGetSymbolAddress((void**)&wqe4h, g_wqe4h);
    cudaGetSymbolAddress((void**)&wqe4l, g_wqe4l);
    cudaGetSymbolAddress((void**)&ohp,   g_ohp);
    cudaGetSymbolAddress((void**)&oe4h,  g_oe4h);
    cudaGetSymbolAddress((void**)&oe4l,  g_oe4l);
    cudaGetSymbolAddress((void**)&wohp,  g_wohp);
    cudaGetSymbolAddress((void**)&woe4h, g_woe4h);
    cudaGetSymbolAddress((void**)&woe4l, g_woe4l);
    cudaGetSymbolAddress((void**)&of32,  g_of32);

    // Operand prep
    split_ax<<<4096, 256>>>(x, xhp, xe4h, xe4l, 4096*256);
    split_w<<<dim3(3072/256, 256), 256>>>(W_qkv, wqhp, wqe4h, wqe4l, 3072);
    maskpack<<<(2*2048*64)/256, 256>>>(mask);

    // QKV projection (fp16 + fused-fp8 cross) -> packed bf16 Q/K/Vt
    gemm_f16fp8<0><<<dim3(24, 32), 256, GEMM_SMEM>>>(xhp, xe4h, xe4l,
                                                     wqhp, wqe4h, wqe4l,
                                                     b_qkv, nullptr, 3072);

    // V repack
    vrepack<<<(32*1024*64)/256, 256>>>();

    // Attention (bf16x3) -> g_of32
    attn_mma_kernel<<<dim3(16, 32), 256, ATTN_SMEM>>>();

    // Out-proj operand prep + GEMM
    split_ax<<<4096, 256>>>(of32, ohp, oe4h, oe4l, 4096*256);
    split_w<<<dim3(1024/256, 256), 256>>>(W_out, wohp, woe4h, woe4l, 1024);
    gemm_f16fp8<1><<<dim3(8, 32), 256, GEMM_SMEM>>>(ohp, oe4h, oe4l,
                                                    wohp, woe4h, woe4l,
                                                    b_out, out, 1024);
}